// round 6
// baseline (speedup 1.0000x reference)
#include <cuda_runtime.h>
#include <cuda_bf16.h>
#include <cstdint>

#define DIM 256
#define MT 16384
#define NTOT 4096
#define TH_GAP 2e-3f
#define NSTAGES 256          // 32 n-chunks(128 codes) * 8 k-chunks(32)
#define SM_A_HI 0
#define SM_A_LO 32768
#define SM_B    65536
#define STAGE_BYTES 16384    // 128n x 32k bf16, hi(8KB)+lo(8KB)
#define SMEM_TOTAL 98304

__device__ __nv_bfloat16 g_Whi[(size_t)NTOT*DIM];
__device__ __nv_bfloat16 g_Wlo[(size_t)NTOT*DIM];
__device__ float  g_WT[(size_t)DIM*NTOT];
__device__ float  g_c2[NTOT];
__device__ float  g_v2[MT];
__device__ int    g_code[MT];
__device__ int    g_fb[MT];
__device__ int    g_fbn;
__device__ double g_loss;

__device__ __forceinline__ uint32_t smem_u32(const void* p){
    uint32_t a; asm("{ .reg .u64 t; cvta.to.shared.u64 t,%1; cvt.u32.u64 %0,t; }":"=r"(a):"l"(p)); return a;
}
__device__ __forceinline__ void ldsm4(uint32_t a, uint32_t* r){
    asm volatile("ldmatrix.sync.aligned.m8n8.x4.shared.b16 {%0,%1,%2,%3},[%4];"
        :"=r"(r[0]),"=r"(r[1]),"=r"(r[2]),"=r"(r[3]):"r"(a));
}
__device__ __forceinline__ void mma16816(float* c, const uint32_t* a, uint32_t b0, uint32_t b1){
    asm volatile("mma.sync.aligned.m16n8k16.row.col.f32.bf16.bf16.f32 "
        "{%0,%1,%2,%3},{%4,%5,%6,%7},{%8,%9},{%0,%1,%2,%3};"
        :"+f"(c[0]),"+f"(c[1]),"+f"(c[2]),"+f"(c[3])
        :"r"(a[0]),"r"(a[1]),"r"(a[2]),"r"(a[3]),"r"(b0),"r"(b1));
}
__device__ __forceinline__ uint32_t packbf(__nv_bfloat16 a, __nv_bfloat16 b){
    return (uint32_t)__bfloat16_as_ushort(a) | ((uint32_t)__bfloat16_as_ushort(b)<<16);
}
__device__ __forceinline__ unsigned ordf(float s){
    unsigned u=__float_as_uint(s);
    return (u&0x80000000u)?~u:(u|0x80000000u);
}
__device__ __forceinline__ float keyf(unsigned long long k){
    unsigned u=(unsigned)(k>>32);
    return (u&0x80000000u)?__uint_as_float(u&0x7FFFFFFFu):__uint_as_float(~u);
}

// ---------- prep ----------
__global__ void k_zero(double* pl, int* pc){ if(threadIdx.x==0){ *pl=0.0; *pc=0; } }

__global__ void k_transpose(const float* __restrict__ src, float* __restrict__ dst, int R){
    __shared__ float tile[32][33];
    int kb=blockIdx.x*32, rb=blockIdx.y*32, tx=threadIdx.x, ty=threadIdx.y;
    #pragma unroll
    for(int j=0;j<32;j+=8) tile[ty+j][tx]=src[(size_t)(rb+ty+j)*DIM+kb+tx];
    __syncthreads();
    #pragma unroll
    for(int j=0;j<32;j+=8) dst[(size_t)(kb+ty+j)*R+rb+tx]=tile[tx][ty+j];
}

__global__ void k_sumsq(const float* __restrict__ src, float* __restrict__ out, int R){
    int row=blockIdx.x*8+threadIdx.y; if(row>=R)return;
    int lane=threadIdx.x; const float* p=src+(size_t)row*DIM; float s=0.f;
    #pragma unroll
    for(int i=0;i<DIM;i+=32){ float x=p[i+lane]; s=fmaf(x,x,s); }
    #pragma unroll
    for(int o=16;o;o>>=1) s+=__shfl_xor_sync(0xffffffffu,s,o);
    if(lane==0) out[row]=s;
}

__global__ void k_wsplit(const float* __restrict__ w, __nv_bfloat16* __restrict__ hi,
                         __nv_bfloat16* __restrict__ lo){
    int i=blockIdx.x*256+threadIdx.x;
    float f=w[i];
    __nv_bfloat16 h=__float2bfloat16(f);
    hi[i]=h; lo[i]=__float2bfloat16(f-__bfloat162float(h));
}

// ---------- main GEMM + argmin ----------
__global__ void __launch_bounds__(256,2)
k_main(const float* __restrict__ v, const __nv_bfloat16* __restrict__ Whi,
       const __nv_bfloat16* __restrict__ Wlo, const float* __restrict__ c2)
{
    extern __shared__ char smem[];
    uint32_t sb=smem_u32(smem);
    const int tid=threadIdx.x, lane=tid&31, wid=tid>>5;
    const int wm=wid>>2, wn=wid&3, q=lane&3;
    const int row0=blockIdx.x*64;
    const uint32_t swz=(uint32_t)(lane&7);

    // fill A panel: 64 rows x 256k, hi+lo bf16, 16B-unit swizzled (row-major 512B rows)
    #pragma unroll
    for(int it=0;it<8;it++){
        int i=tid+it*256, r=i>>5, u=i&31;
        const float4* vp=(const float4*)(v+(size_t)(row0+r)*DIM+u*8);
        float4 f0=vp[0], f1=vp[1];
        float fs[8]={f0.x,f0.y,f0.z,f0.w,f1.x,f1.y,f1.z,f1.w};
        uint32_t hp[4], lp[4];
        #pragma unroll
        for(int j=0;j<4;j++){
            __nv_bfloat16 h0=__float2bfloat16(fs[2*j]), h1=__float2bfloat16(fs[2*j+1]);
            hp[j]=packbf(h0,h1);
            lp[j]=packbf(__float2bfloat16(fs[2*j]-__bfloat162float(h0)),
                         __float2bfloat16(fs[2*j+1]-__bfloat162float(h1)));
        }
        uint32_t byte=(uint32_t)r*512u+(uint32_t)((u^(r&7))<<4);
        *(uint4*)(smem+SM_A_HI+byte)=make_uint4(hp[0],hp[1],hp[2],hp[3]);
        *(uint4*)(smem+SM_A_LO+byte)=make_uint4(lp[0],lp[1],lp[2],lp[3]);
    }

    // stage: 128 codes x 32k, hi(8KB)+lo(8KB), 64B rows, swizzle u^((n>>1)&3)
    auto ld_stage=[&](int s){
        int nc=s>>3, kc=(s&7)*32;
        uint32_t base=sb+SM_B+(uint32_t)(s&1)*STAGE_BYTES;
        #pragma unroll
        for(int j=0;j<4;j++){
            int idx=j*256+tid, mat=idx>>9, rem=idx&511, n=rem>>2, u=rem&3;
            const __nv_bfloat16* src=(mat?Wlo:Whi)+(size_t)(nc*128+n)*DIM+kc+u*8;
            uint32_t dst=base+(uint32_t)mat*8192u+(uint32_t)n*64u
                         +(uint32_t)((u^((n>>1)&3))<<4);
            asm volatile("cp.async.cg.shared.global [%0],[%1],16;"::"r"(dst),"l"(src):"memory");
        }
        asm volatile("cp.async.commit_group;":::"memory");
    };
    ld_stage(0);

    // per-lane ldmatrix bases
    const uint32_t rA=(uint32_t)(wm*32+(lane&7)+((lane>>3)&1)*8);
    const uint32_t aH0=sb+SM_A_HI+rA*512u, aH1=aH0+16u*512u;
    const uint32_t aL0=sb+SM_A_LO+rA*512u, aL1=aL0+16u*512u;
    const uint32_t nB=(uint32_t)(wn*32+(lane&7)+((lane>>4)&1)*8);
    const uint32_t bxor=(nB>>1)&3u;
    const uint32_t khA=(uint32_t)((lane>>4)&1), khB=(uint32_t)((lane>>3)&1);

    float acc[2][4][4];
    float s1[4]={3.4e38f,3.4e38f,3.4e38f,3.4e38f};
    float s2[4]={3.4e38f,3.4e38f,3.4e38f,3.4e38f};
    int   c1[4]={1,1,1,1};

    #pragma unroll 1
    for(int s=0;s<NSTAGES;s++){
        if(s+1<NSTAGES){ ld_stage(s+1); asm volatile("cp.async.wait_group 1;":::"memory"); }
        else           { asm volatile("cp.async.wait_group 0;":::"memory"); }
        __syncthreads();

        if((s&7)==0){
            #pragma unroll
            for(int m=0;m<2;m++)
            #pragma unroll
            for(int n=0;n<4;n++){acc[m][n][0]=0.f;acc[m][n][1]=0.f;acc[m][n][2]=0.f;acc[m][n][3]=0.f;}
        }
        const uint32_t bbase=sb+SM_B+(uint32_t)(s&1)*STAGE_BYTES+nB*64u;
        const uint32_t ukA=(uint32_t)((s&7)*4)+khA;

        #pragma unroll
        for(int ks=0;ks<2;ks++){
            uint32_t ah0[4],ah1[4],al0[4],al1[4],bh0[4],bh1[4],bl0[4],bl1[4];
            uint32_t oA=(uint32_t)(((ukA+ks*2)^swz)<<4);
            ldsm4(aH0+oA,ah0); ldsm4(aH1+oA,ah1);
            ldsm4(aL0+oA,al0); ldsm4(aL1+oA,al1);
            uint32_t oB=(uint32_t)((((khB+ks*2)^bxor))<<4);
            ldsm4(bbase+oB,bh0);        ldsm4(bbase+16u*64u+oB,bh1);
            ldsm4(bbase+8192u+oB,bl0);  ldsm4(bbase+8192u+16u*64u+oB,bl1);
            #pragma unroll
            for(int nt=0;nt<4;nt++){
                uint32_t b0=(nt<2?bh0:bh1)[(nt&1)*2], b1=(nt<2?bh0:bh1)[(nt&1)*2+1];
                uint32_t l0=(nt<2?bl0:bl1)[(nt&1)*2], l1=(nt<2?bl0:bl1)[(nt&1)*2+1];
                mma16816(acc[0][nt],ah0,b0,b1);
                mma16816(acc[0][nt],al0,b0,b1);
                mma16816(acc[0][nt],ah0,l0,l1);
                mma16816(acc[1][nt],ah1,b0,b1);
                mma16816(acc[1][nt],al1,b0,b1);
                mma16816(acc[1][nt],ah1,l0,l1);
            }
        }

        if((s&7)==7){
            int cb=(s>>3)*128;
            #pragma unroll
            for(int mt=0;mt<2;mt++)
            #pragma unroll
            for(int nt=0;nt<4;nt++){
                int c=cb+wn*32+nt*8+q*2;
                float c20=__ldg(c2+c), c21=__ldg(c2+c+1);
                float sc;
                sc=fmaf(-2.f,acc[mt][nt][0],c20);
                if(c!=0){ if(sc<s1[mt*2]){s2[mt*2]=s1[mt*2];s1[mt*2]=sc;c1[mt*2]=c;} else if(sc<s2[mt*2])s2[mt*2]=sc; }
                sc=fmaf(-2.f,acc[mt][nt][2],c20);
                if(c!=0){ if(sc<s1[mt*2+1]){s2[mt*2+1]=s1[mt*2+1];s1[mt*2+1]=sc;c1[mt*2+1]=c;} else if(sc<s2[mt*2+1])s2[mt*2+1]=sc; }
                sc=fmaf(-2.f,acc[mt][nt][1],c21);
                if(sc<s1[mt*2]){s2[mt*2]=s1[mt*2];s1[mt*2]=sc;c1[mt*2]=c+1;} else if(sc<s2[mt*2])s2[mt*2]=sc;
                sc=fmaf(-2.f,acc[mt][nt][3],c21);
                if(sc<s1[mt*2+1]){s2[mt*2+1]=s1[mt*2+1];s1[mt*2+1]=sc;c1[mt*2+1]=c+1;} else if(sc<s2[mt*2+1])s2[mt*2+1]=sc;
            }
        }
        __syncthreads();
    }

    // quad reduce (lanes q=0..3 hold same rows)
    unsigned long long key[4];
    #pragma unroll
    for(int r=0;r<4;r++) key[r]=((unsigned long long)ordf(s1[r])<<32)|(unsigned)c1[r];
    #pragma unroll
    for(int o=1;o<=2;o<<=1){
        #pragma unroll
        for(int r=0;r<4;r++){
            unsigned long long ko=__shfl_xor_sync(0xffffffffu,key[r],o);
            float s2o=__shfl_xor_sync(0xffffffffu,s2[r],o);
            unsigned long long kmx=key[r]>ko?key[r]:ko;
            key[r]=key[r]<ko?key[r]:ko;
            s2[r]=fminf(fminf(s2[r],s2o),keyf(kmx));
        }
    }
    // cross-warp reduce via smem scratch (A region reuse; all A reads done)
    unsigned long long* skey=(unsigned long long*)smem;     // [64][4]
    float* ss2=(float*)(smem+2048);                         // [64][4]
    if(q==0){
        #pragma unroll
        for(int r=0;r<4;r++){
            int rowl=wm*32+(r>>1)*16+(lane>>2)+(r&1)*8;
            skey[rowl*4+wn]=key[r];
            ss2 [rowl*4+wn]=s2[r];
        }
    }
    __syncthreads();
    if(tid<64){
        unsigned long long k=skey[tid*4];
        float sm=ss2[tid*4];
        #pragma unroll
        for(int i=1;i<4;i++){
            unsigned long long ko=skey[tid*4+i];
            unsigned long long kmx=k>ko?k:ko;
            k=k<ko?k:ko;
            sm=fminf(fminf(sm,ss2[tid*4+i]),keyf(kmx));
        }
        int row=row0+tid;
        g_code[row]=(int)(k&0xFFFFFFFFu);
        if(sm-keyf(k)<TH_GAP){ int p=atomicAdd(&g_fbn,1); g_fb[p]=row; }
    }
}

// ---------- exact fp32 fallback ----------
__global__ void k_fb(const float* __restrict__ v, const float* __restrict__ WT,
                     const float* __restrict__ c2, const float* __restrict__ v2){
    __shared__ float vs[DIM];
    __shared__ unsigned long long red[256];
    int nfb=g_fbn;
    for(int it=blockIdx.x; it<nfb; it+=gridDim.x){
        int row=g_fb[it];
        for(int i=threadIdx.x;i<DIM;i+=256) vs[i]=v[(size_t)row*DIM+i];
        __syncthreads();
        float v2r=v2[row];
        unsigned long long best=~0ULL;
        for(int n=threadIdx.x;n<NTOT;n+=256){
            if(n==0) continue;
            float dot=0.f;
            #pragma unroll 8
            for(int k=0;k<DIM;k++) dot=fmaf(vs[k],WT[(size_t)k*NTOT+n],dot);
            float s=__fadd_rn(__fsub_rn(v2r,__fmul_rn(2.0f,dot)),c2[n]);
            unsigned long long ky=((unsigned long long)ordf(s)<<32)|(unsigned)n;
            if(ky<best)best=ky;
        }
        red[threadIdx.x]=best; __syncthreads();
        #pragma unroll
        for(int o=128;o;o>>=1){
            if(threadIdx.x<o && red[threadIdx.x+o]<red[threadIdx.x]) red[threadIdx.x]=red[threadIdx.x+o];
            __syncthreads();
        }
        if(threadIdx.x==0) g_code[row]=(int)(red[0]&0xFFFFFFFFu);
        __syncthreads();
    }
}

// ---------- gather + loss ----------
__global__ void k_gather(const float* __restrict__ v, const float* __restrict__ w,
                         float* __restrict__ dout, double* __restrict__ lossAcc,
                         long long idxBase){
    int wy=threadIdx.y, lane=threadIdx.x;
    int row=blockIdx.x*8+wy;
    const float4* vr=(const float4*)(v+(size_t)row*DIM);
    float4 x0=vr[lane*2], x1=vr[lane*2+1];
    const float CEQ=0.00390625f;
    bool alleq=(x0.x==CEQ)&&(x0.y==CEQ)&&(x0.z==CEQ)&&(x0.w==CEQ)&&
               (x1.x==CEQ)&&(x1.y==CEQ)&&(x1.z==CEQ)&&(x1.w==CEQ);
    int code=g_code[row];
    if(__all_sync(0xffffffffu,alleq)) code=0;
    const float4* cr=(const float4*)(w+(size_t)code*DIM);
    float4 o0=cr[lane*2], o1=cr[lane*2+1];
    float4* orow=(float4*)(dout+(size_t)row*DIM);
    orow[lane*2]=o0; orow[lane*2+1]=o1;
    if(idxBase>=0&&lane==0) dout[idxBase+row]=(float)code;
    double ls=0.0; float d;
    d=o0.x-x0.x; ls+=(double)d*d; d=o0.y-x0.y; ls+=(double)d*d;
    d=o0.z-x0.z; ls+=(double)d*d; d=o0.w-x0.w; ls+=(double)d*d;
    d=o1.x-x1.x; ls+=(double)d*d; d=o1.y-x1.y; ls+=(double)d*d;
    d=o1.z-x1.z; ls+=(double)d*d; d=o1.w-x1.w; ls+=(double)d*d;
    #pragma unroll
    for(int o=16;o;o>>=1) ls+=__shfl_xor_sync(0xffffffffu,ls,o);
    if(lane==0) atomicAdd(lossAcc,ls);
}

__global__ void k_fin(float* dout, const double* lossAcc,
                      long long lossPos, long long usedPos, double invCnt){
    if(threadIdx.x==0){
        if(lossPos>=0) dout[lossPos]=(float)(*lossAcc*invCnt);
        if(usedPos>=0) dout[usedPos]=0.0f;
    }
}

extern "C" void kernel_launch(void* const* d_in, const int* in_sizes, int n_in,
                              void* d_out, int out_size)
{
    const float* v=(const float*)d_in[0];
    const float* w=(const float*)d_in[1];
    const int M=in_sizes[0]/DIM, N=in_sizes[1]/DIM;
    float* out=(float*)d_out;

    __nv_bfloat16 *pWhi,*pWlo; float *pWT,*pC2,*pV2; int* pFbn; double* pLoss;
    cudaGetSymbolAddress((void**)&pWhi,g_Whi);
    cudaGetSymbolAddress((void**)&pWlo,g_Wlo);
    cudaGetSymbolAddress((void**)&pWT,g_WT);
    cudaGetSymbolAddress((void**)&pC2,g_c2);
    cudaGetSymbolAddress((void**)&pV2,g_v2);
    cudaGetSymbolAddress((void**)&pFbn,g_fbn);
    cudaGetSymbolAddress((void**)&pLoss,g_loss);

    long long base=(long long)M*DIM;
    long long idxBase=-1,lossPos=-1,usedPos=-1;
    if((long long)out_size>=base+M)   idxBase=base;
    if((long long)out_size>=base+M+1) lossPos=base+M;
    if((long long)out_size>=base+M+2) usedPos=base+M+1;

    dim3 tb(32,8);
    k_zero<<<1,32>>>(pLoss,pFbn);
    k_sumsq<<<M/8,tb>>>(v,pV2,M);
    k_sumsq<<<N/8,tb>>>(w,pC2,N);
    k_transpose<<<dim3(DIM/32,N/32),tb>>>(w,pWT,N);
    k_wsplit<<<(N*DIM)/256,256>>>(w,pWhi,pWlo);

    cudaFuncSetAttribute(k_main,cudaFuncAttributeMaxDynamicSharedMemorySize,SMEM_TOTAL);
    k_main<<<M/64,256,SMEM_TOTAL>>>(v,pWhi,pWlo,pC2);

    k_fb<<<256,256>>>(v,pWT,pC2,pV2);
    k_gather<<<M/8,tb>>>(v,w,out,pLoss,idxBase);
    k_fin<<<1,32>>>(out,pLoss,lossPos,usedPos,1.0/((double)M*DIM));
}

// round 7
// speedup vs baseline: 1.4716x; 1.4716x over previous
#include <cuda_runtime.h>
#include <cuda_bf16.h>
#include <cstdint>

#define DIM 256
#define MT 16384
#define NTOT 4096
#define KSC 0.0080f
#define EPS 5e-4f
#define NSTAGES 128          // 32 n-chunks(128 codes) * 4 k-chunks(64)
#define SM_B 32768
#define STAGE_BYTES 16384    // 128n x 64k bf16 hi
#define SMEM_TOTAL 65536

__device__ float g_dots[(size_t)MT*NTOT];     // 256MB score scratch
__device__ __nv_bfloat16 g_Whi[(size_t)NTOT*DIM];
__device__ float  g_c2[NTOT];
__device__ float  g_sq[NTOT];
__device__ float  g_v2[MT];
__device__ int    g_code[MT];
__device__ int    g_fb[MT];
__device__ int    g_fbn;
__device__ double g_loss;

__device__ __forceinline__ uint32_t smem_u32(const void* p){
    uint32_t a; asm("{ .reg .u64 t; cvta.to.shared.u64 t,%1; cvt.u32.u64 %0,t; }":"=r"(a):"l"(p)); return a;
}
__device__ __forceinline__ void ldsm4(uint32_t a, uint32_t* r){
    asm volatile("ldmatrix.sync.aligned.m8n8.x4.shared.b16 {%0,%1,%2,%3},[%4];"
        :"=r"(r[0]),"=r"(r[1]),"=r"(r[2]),"=r"(r[3]):"r"(a));
}
__device__ __forceinline__ void mma16816(float* c, const uint32_t* a, uint32_t b0, uint32_t b1){
    asm volatile("mma.sync.aligned.m16n8k16.row.col.f32.bf16.bf16.f32 "
        "{%0,%1,%2,%3},{%4,%5,%6,%7},{%8,%9},{%0,%1,%2,%3};"
        :"+f"(c[0]),"+f"(c[1]),"+f"(c[2]),"+f"(c[3])
        :"r"(a[0]),"r"(a[1]),"r"(a[2]),"r"(a[3]),"r"(b0),"r"(b1));
}
__device__ __forceinline__ uint32_t packbf(__nv_bfloat16 a, __nv_bfloat16 b){
    return (uint32_t)__bfloat16_as_ushort(a) | ((uint32_t)__bfloat16_as_ushort(b)<<16);
}
__device__ __forceinline__ unsigned ordf(float s){
    unsigned u=__float_as_uint(s);
    return (u&0x80000000u)?~u:(u|0x80000000u);
}
__device__ __forceinline__ float keyf(unsigned long long k){
    unsigned u=(unsigned)(k>>32);
    return (u&0x80000000u)?__uint_as_float(u&0x7FFFFFFFu):__uint_as_float(~u);
}

// ---------- prep ----------
__global__ void k_zero(double* pl, int* pc){ if(threadIdx.x==0){ *pl=0.0; *pc=0; } }

__global__ void k_sumsq(const float* __restrict__ src, float* __restrict__ out,
                        float* __restrict__ sqout, int R){
    int row=blockIdx.x*8+threadIdx.y; if(row>=R)return;
    int lane=threadIdx.x; const float* p=src+(size_t)row*DIM; float s=0.f;
    #pragma unroll
    for(int i=0;i<DIM;i+=32){ float x=p[i+lane]; s=fmaf(x,x,s); }
    #pragma unroll
    for(int o=16;o;o>>=1) s+=__shfl_xor_sync(0xffffffffu,s,o);
    if(lane==0){ out[row]=s; if(sqout) sqout[row]=sqrtf(s); }
}

__global__ void k_whi(const float* __restrict__ w, __nv_bfloat16* __restrict__ hi){
    int i=blockIdx.x*256+threadIdx.x;
    hi[i]=__float2bfloat16(w[i]);
}

// ---------- main GEMM: dots = v_hi . w_hi (bf16 HMMA, fp32 acc) ----------
__global__ void __launch_bounds__(256,2)
k_main(const float* __restrict__ v, const __nv_bfloat16* __restrict__ Whi)
{
    extern __shared__ char smem[];
    uint32_t sb=smem_u32(smem);
    const int tid=threadIdx.x, lane=tid&31, wid=tid>>5;
    const int wm=wid>>2, wn=wid&3, q=lane&3;
    const int row0=blockIdx.x*64;
    const uint32_t swz=(uint32_t)(lane&7);

    // A panel: 64 rows x 256k hi bf16, 512B rows, 16B-unit swizzle u^(r&7)
    #pragma unroll
    for(int it=0;it<8;it++){
        int i=tid+it*256, r=i>>5, u=i&31;
        const float4* vp=(const float4*)(v+(size_t)(row0+r)*DIM+u*8);
        float4 f0=vp[0], f1=vp[1];
        float fs[8]={f0.x,f0.y,f0.z,f0.w,f1.x,f1.y,f1.z,f1.w};
        uint32_t hp[4];
        #pragma unroll
        for(int j=0;j<4;j++)
            hp[j]=packbf(__float2bfloat16(fs[2*j]),__float2bfloat16(fs[2*j+1]));
        uint32_t byte=(uint32_t)r*512u+(uint32_t)((u^(r&7))<<4);
        *(uint4*)(smem+byte)=make_uint4(hp[0],hp[1],hp[2],hp[3]);
    }

    // B stage: 128 codes x 64k hi, 128B rows, swizzle u^(n&7)
    auto ld_stage=[&](int s){
        int nc=s>>2, kc=(s&3)*64;
        uint32_t base=sb+SM_B+(uint32_t)(s&1)*STAGE_BYTES;
        #pragma unroll
        for(int j=0;j<4;j++){
            int idx=j*256+tid, n=idx>>3, u=idx&7;
            const __nv_bfloat16* src=Whi+(size_t)(nc*128+n)*DIM+kc+u*8;
            uint32_t dst=base+(uint32_t)n*128u+(uint32_t)((u^(n&7))<<4);
            asm volatile("cp.async.cg.shared.global [%0],[%1],16;"::"r"(dst),"l"(src):"memory");
        }
        asm volatile("cp.async.commit_group;":::"memory");
    };
    ld_stage(0);

    const uint32_t rA=(uint32_t)(wm*32+(lane&7)+((lane>>3)&1)*8);
    const uint32_t aH0=sb+rA*512u, aH1=aH0+16u*512u;
    const uint32_t nB=(uint32_t)(wn*32+(lane&7)+((lane>>4)&1)*8);
    const uint32_t khA=(uint32_t)((lane>>4)&1), khB=(uint32_t)((lane>>3)&1);

    float acc[2][4][4];

    #pragma unroll 1
    for(int s=0;s<NSTAGES;s++){
        if(s+1<NSTAGES){ ld_stage(s+1); asm volatile("cp.async.wait_group 1;":::"memory"); }
        else           { asm volatile("cp.async.wait_group 0;":::"memory"); }
        __syncthreads();

        if((s&3)==0){
            #pragma unroll
            for(int m=0;m<2;m++)
            #pragma unroll
            for(int n=0;n<4;n++){acc[m][n][0]=0.f;acc[m][n][1]=0.f;acc[m][n][2]=0.f;acc[m][n][3]=0.f;}
        }
        const uint32_t bbase=sb+SM_B+(uint32_t)(s&1)*STAGE_BYTES+nB*128u;
        const uint32_t ukA=(uint32_t)((s&3)*8)+khA;

        #pragma unroll
        for(int ks=0;ks<4;ks++){
            uint32_t ah0[4],ah1[4],bf0[4],bf1[4];
            uint32_t oA=(uint32_t)(((ukA+ks*2)^swz)<<4);
            ldsm4(aH0+oA,ah0); ldsm4(aH1+oA,ah1);
            uint32_t oB=(uint32_t)((((khB+ks*2))^swz)<<4);
            ldsm4(bbase+oB,bf0); ldsm4(bbase+16u*128u+oB,bf1);
            #pragma unroll
            for(int nt=0;nt<4;nt++){
                uint32_t b0=(nt<2?bf0:bf1)[(nt&1)*2], b1=(nt<2?bf0:bf1)[(nt&1)*2+1];
                mma16816(acc[0][nt],ah0,b0,b1);
                mma16816(acc[1][nt],ah1,b0,b1);
            }
        }

        if((s&3)==3){
            int cb=(s>>2)*128;
            #pragma unroll
            for(int mt=0;mt<2;mt++){
                int rb=row0+wm*32+mt*16+(lane>>2);
                #pragma unroll
                for(int nt=0;nt<4;nt++){
                    int c=cb+wn*32+nt*8+q*2;
                    *(float2*)(g_dots+(size_t)rb*NTOT+c)    =make_float2(acc[mt][nt][0],acc[mt][nt][1]);
                    *(float2*)(g_dots+(size_t)(rb+8)*NTOT+c)=make_float2(acc[mt][nt][2],acc[mt][nt][3]);
                }
            }
        }
        __syncthreads();
    }
}

// ---------- certify per row; uncertain rows -> g_fb ----------
__global__ void k_sel(const float* __restrict__ c2, const float* __restrict__ sq,
                      const float* __restrict__ v2){
    int lane=threadIdx.x&31, w=threadIdx.x>>5;
    int row=blockIdx.x*8+w;
    float v2r=v2[row], kv=KSC*sqrtf(v2r);
    const float* dr=g_dots+(size_t)row*NTOT;
    unsigned long long key1=~0ULL, lk1=~0ULL, lk2=~0ULL; float u1=3.4e38f;
    #pragma unroll 4
    for(int i=0;i<NTOT/32;i++){
        int n=lane+i*32;
        if(n==0) continue;
        float dot=dr[n];
        float s=__fadd_rn(__fsub_rn(v2r,__fmul_rn(2.f,dot)),__ldg(c2+n));
        float m=fmaf(kv,__ldg(sq+n),EPS);
        unsigned long long ks=((unsigned long long)ordf(s)<<32)|(unsigned)n;
        if(ks<key1){key1=ks; u1=s+m;}
        unsigned long long kl=((unsigned long long)ordf(s-m)<<32)|(unsigned)n;
        if(kl<lk1){lk2=lk1;lk1=kl;} else if(kl<lk2) lk2=kl;
    }
    #pragma unroll
    for(int o=16;o;o>>=1){
        unsigned long long ok=__shfl_xor_sync(0xffffffffu,key1,o);
        float ou=__shfl_xor_sync(0xffffffffu,u1,o);
        if(ok<key1){key1=ok;u1=ou;}
        unsigned long long o1=__shfl_xor_sync(0xffffffffu,lk1,o);
        unsigned long long o2=__shfl_xor_sync(0xffffffffu,lk2,o);
        unsigned long long mx=lk1>o1?lk1:o1;
        lk1=lk1<o1?lk1:o1;
        unsigned long long t=lk2<o2?lk2:o2;
        lk2=t<mx?t:mx;
    }
    if(lane==0){
        int c1=(int)(key1&0xFFFFFFFFu);
        unsigned long long lx=((int)(lk1&0xFFFFFFFFu)==c1)?lk2:lk1;
        if(u1<keyf(lx)) g_code[row]=c1;
        else { int p=atomicAdd(&g_fbn,1); g_fb[p]=row; }
    }
}

// ---------- candidate-exact rescore for uncertain rows ----------
__global__ void k_fbc(const float* __restrict__ v, const float* __restrict__ w,
                      const float* __restrict__ c2, const float* __restrict__ sq,
                      const float* __restrict__ v2){
    __shared__ float vs[DIM];
    __shared__ unsigned long long rk[256];
    __shared__ float ru[256];
    __shared__ int cnt, cands[64];
    int tid=threadIdx.x;
    int nfb=g_fbn;
    for(int it=blockIdx.x; it<nfb; it+=gridDim.x){
        int row=g_fb[it];
        float v2r=v2[row], kv=KSC*sqrtf(v2r);
        const float* dr=g_dots+(size_t)row*NTOT;
        for(int i=tid;i<DIM;i+=256) vs[i]=v[(size_t)row*DIM+i];
        // phase1: approx best + its upper bound
        unsigned long long k1=~0ULL; float u1=3.4e38f;
        for(int n=tid;n<NTOT;n+=256){
            if(n==0) continue;
            float s=__fadd_rn(__fsub_rn(v2r,__fmul_rn(2.f,dr[n])),c2[n]);
            unsigned long long ks=((unsigned long long)ordf(s)<<32)|(unsigned)n;
            if(ks<k1){k1=ks; u1=s+fmaf(kv,sq[n],EPS);}
        }
        rk[tid]=k1; ru[tid]=u1; __syncthreads();
        for(int o=128;o;o>>=1){
            if(tid<o && rk[tid+o]<rk[tid]){rk[tid]=rk[tid+o];ru[tid]=ru[tid+o];}
            __syncthreads();
        }
        float U=ru[0];
        if(tid==0) cnt=0;
        __syncthreads();
        // phase2: collect candidates with lower bound <= U
        for(int n=tid;n<NTOT;n+=256){
            if(n==0) continue;
            float s=__fadd_rn(__fsub_rn(v2r,__fmul_rn(2.f,dr[n])),c2[n]);
            float l=s-fmaf(kv,sq[n],EPS);
            if(l<=U){ int p=atomicAdd(&cnt,1); if(p<64) cands[p]=n; }
        }
        __syncthreads();
        int nc=cnt;
        unsigned long long bk=~0ULL;
        if(nc<=64){
            if(tid<nc){
                int n=cands[tid];
                float dot=0.f;
                #pragma unroll 8
                for(int k=0;k<DIM;k++) dot=fmaf(vs[k],__ldg(w+(size_t)n*DIM+k),dot);
                float s=__fadd_rn(__fsub_rn(v2r,__fmul_rn(2.f,dot)),c2[n]);
                bk=((unsigned long long)ordf(s)<<32)|(unsigned)n;
            }
        } else {
            for(int n=tid;n<NTOT;n+=256){
                if(n==0) continue;
                float dot=0.f;
                #pragma unroll 8
                for(int k=0;k<DIM;k++) dot=fmaf(vs[k],__ldg(w+(size_t)n*DIM+k),dot);
                float s=__fadd_rn(__fsub_rn(v2r,__fmul_rn(2.f,dot)),c2[n]);
                unsigned long long ky=((unsigned long long)ordf(s)<<32)|(unsigned)n;
                if(ky<bk)bk=ky;
            }
        }
        rk[tid]=bk; __syncthreads();
        for(int o=128;o;o>>=1){
            if(tid<o && rk[tid+o]<rk[tid]) rk[tid]=rk[tid+o];
            __syncthreads();
        }
        if(tid==0) g_code[row]=(int)(rk[0]&0xFFFFFFFFu);
        __syncthreads();
    }
}

// ---------- gather + loss ----------
__global__ void k_gather(const float* __restrict__ v, const float* __restrict__ w,
                         float* __restrict__ dout, double* __restrict__ lossAcc,
                         long long idxBase){
    int wy=threadIdx.y, lane=threadIdx.x;
    int row=blockIdx.x*8+wy;
    const float4* vr=(const float4*)(v+(size_t)row*DIM);
    float4 x0=vr[lane*2], x1=vr[lane*2+1];
    const float CEQ=0.00390625f;
    bool alleq=(x0.x==CEQ)&&(x0.y==CEQ)&&(x0.z==CEQ)&&(x0.w==CEQ)&&
               (x1.x==CEQ)&&(x1.y==CEQ)&&(x1.z==CEQ)&&(x1.w==CEQ);
    int code=g_code[row];
    if(__all_sync(0xffffffffu,alleq)) code=0;
    const float4* cr=(const float4*)(w+(size_t)code*DIM);
    float4 o0=cr[lane*2], o1=cr[lane*2+1];
    float4* orow=(float4*)(dout+(size_t)row*DIM);
    orow[lane*2]=o0; orow[lane*2+1]=o1;
    if(idxBase>=0&&lane==0) dout[idxBase+row]=(float)code;
    double ls=0.0; float d;
    d=o0.x-x0.x; ls+=(double)d*d; d=o0.y-x0.y; ls+=(double)d*d;
    d=o0.z-x0.z; ls+=(double)d*d; d=o0.w-x0.w; ls+=(double)d*d;
    d=o1.x-x1.x; ls+=(double)d*d; d=o1.y-x1.y; ls+=(double)d*d;
    d=o1.z-x1.z; ls+=(double)d*d; d=o1.w-x1.w; ls+=(double)d*d;
    #pragma unroll
    for(int o=16;o;o>>=1) ls+=__shfl_xor_sync(0xffffffffu,ls,o);
    if(lane==0) atomicAdd(lossAcc,ls);
}

__global__ void k_fin(float* dout, const double* lossAcc,
                      long long lossPos, long long usedPos, double invCnt){
    if(threadIdx.x==0){
        if(lossPos>=0) dout[lossPos]=(float)(*lossAcc*invCnt);
        if(usedPos>=0) dout[usedPos]=0.0f;
    }
}

extern "C" void kernel_launch(void* const* d_in, const int* in_sizes, int n_in,
                              void* d_out, int out_size)
{
    const float* v=(const float*)d_in[0];
    const float* w=(const float*)d_in[1];
    const int M=in_sizes[0]/DIM, N=in_sizes[1]/DIM;
    float* out=(float*)d_out;

    __nv_bfloat16* pWhi; float *pC2,*pSq,*pV2; int* pFbn; double* pLoss;
    cudaGetSymbolAddress((void**)&pWhi,g_Whi);
    cudaGetSymbolAddress((void**)&pC2,g_c2);
    cudaGetSymbolAddress((void**)&pSq,g_sq);
    cudaGetSymbolAddress((void**)&pV2,g_v2);
    cudaGetSymbolAddress((void**)&pFbn,g_fbn);
    cudaGetSymbolAddress((void**)&pLoss,g_loss);

    long long base=(long long)M*DIM;
    long long idxBase=-1,lossPos=-1,usedPos=-1;
    if((long long)out_size>=base+M)   idxBase=base;
    if((long long)out_size>=base+M+1) lossPos=base+M;
    if((long long)out_size>=base+M+2) usedPos=base+M+1;

    dim3 tb(32,8);
    k_zero<<<1,32>>>(pLoss,pFbn);
    k_sumsq<<<M/8,tb>>>(v,pV2,(float*)nullptr,M);
    k_sumsq<<<N/8,tb>>>(w,pC2,pSq,N);
    k_whi<<<(N*DIM)/256,256>>>(w,pWhi);

    cudaFuncSetAttribute(k_main,cudaFuncAttributeMaxDynamicSharedMemorySize,SMEM_TOTAL);
    k_main<<<M/64,256,SMEM_TOTAL>>>(v,pWhi);

    k_sel<<<M/8,256>>>(pC2,pSq,pV2);
    k_fbc<<<512,256>>>(v,w,pC2,pSq,pV2);
    k_gather<<<M/8,tb>>>(v,w,out,pLoss,idxBase);
    k_fin<<<1,32>>>(out,pLoss,lossPos,usedPos,1.0/((double)M*DIM));
}